// round 1
// baseline (speedup 1.0000x reference)
#include <cuda_runtime.h>
#include <math.h>

// MinDistLoss: out = min_{b,n,m} sqrt(max( xx[b,n] + yy[b,m] - 2*dot(v1[b,n],v2[b,m]), 0 ))
// v1: [B,N,3] f32, v2: [B,M,3] f32, out: scalar f32.
//
// Numeric scheme chosen to mirror the reference (XLA) rounding:
//   xx = (x0*x0 + x1*x1) + x2*x2   (separate mul/add, reduce-style)
//   zz = fma(x2,y2, fma(x1,y1, x0*y0))  (cuBLAS-style ascending fma chain)
//   sq = fma(-2, zz, xx+yy)        (== (xx+yy) - 2*zz exactly: 2*zz is exact)
// min(sqrt(max(sq,0))) == sqrt(max(min(sq),0)) by monotonicity.

#define TN 64
#define TM 128
#define THREADS 256
#define MAX_PARTIALS (1 << 18)   // 262144 >= 16 * ceil(6890/64) * ceil(6890/128) = 93312

__device__ float g_partials[MAX_PARTIALS];

__global__ __launch_bounds__(THREADS)
void pairmin_kernel(const float* __restrict__ v1, const float* __restrict__ v2,
                    int B, int N, int M, float* __restrict__ partials) {
    __shared__ float sax[TN], say[TN], saz[TN], saw[TN];
    __shared__ float sbx[TM], sby[TM], sbz[TM], sbw[TM];

    const int b  = blockIdx.z;
    const int n0 = blockIdx.y * TN;
    const int m0 = blockIdx.x * TM;
    const float* p1 = v1 + (size_t)b * N * 3;
    const float* p2 = v2 + (size_t)b * M * 3;
    const int tid = threadIdx.x;

    // Stage n-tile (clamped indices: duplicate pairs are harmless under min)
    for (int i = tid; i < TN; i += THREADS) {
        int n = n0 + i; if (n > N - 1) n = N - 1;
        float x0 = p1[n * 3 + 0], x1 = p1[n * 3 + 1], x2 = p1[n * 3 + 2];
        sax[i] = x0; say[i] = x1; saz[i] = x2;
        saw[i] = __fadd_rn(__fadd_rn(__fmul_rn(x0, x0), __fmul_rn(x1, x1)),
                           __fmul_rn(x2, x2));
    }
    // Stage m-tile
    for (int i = tid; i < TM; i += THREADS) {
        int m = m0 + i; if (m > M - 1) m = M - 1;
        float y0 = p2[m * 3 + 0], y1 = p2[m * 3 + 1], y2 = p2[m * 3 + 2];
        sbx[i] = y0; sby[i] = y1; sbz[i] = y2;
        sbw[i] = __fadd_rn(__fadd_rn(__fmul_rn(y0, y0), __fmul_rn(y1, y1)),
                           __fmul_rn(y2, y2));
    }
    __syncthreads();

    const int tx = tid & 15;   // m lane (16 lanes, 8 m each, stride 16)
    const int ty = tid >> 4;   // n lane (16 lanes, 4 n each, stride 16)

    float ax[4], ay[4], az[4], aw[4];
#pragma unroll
    for (int i = 0; i < 4; i++) {
        int n = ty + 16 * i;
        ax[i] = sax[n]; ay[i] = say[n]; az[i] = saz[n]; aw[i] = saw[n];
    }
    float bx[8], by[8], bz[8], bw[8];
#pragma unroll
    for (int j = 0; j < 8; j++) {
        int m = tx + 16 * j;
        bx[j] = sbx[m]; by[j] = sby[m]; bz[j] = sbz[m]; bw[j] = sbw[m];
    }

    float best = 3.4028235e38f;
#pragma unroll
    for (int j = 0; j < 8; j++) {
#pragma unroll
        for (int i = 0; i < 4; i++) {
            float dot = __fmaf_rn(az[i], bz[j],
                        __fmaf_rn(ay[i], by[j],
                        __fmul_rn(ax[i], bx[j])));
            float t  = __fadd_rn(aw[i], bw[j]);
            float sq = __fmaf_rn(-2.0f, dot, t);
            best = fminf(best, sq);
        }
    }

    // Warp reduce
#pragma unroll
    for (int off = 16; off; off >>= 1)
        best = fminf(best, __shfl_xor_sync(0xffffffffu, best, off));

    __shared__ float wmin[THREADS / 32];
    if ((tid & 31) == 0) wmin[tid >> 5] = best;
    __syncthreads();
    if (tid == 0) {
        float r = wmin[0];
#pragma unroll
        for (int w = 1; w < THREADS / 32; w++) r = fminf(r, wmin[w]);
        int bidx = (blockIdx.z * gridDim.y + blockIdx.y) * gridDim.x + blockIdx.x;
        partials[bidx] = r;
    }
}

__global__ __launch_bounds__(1024)
void final_reduce_kernel(const float* __restrict__ partials, int n,
                         float* __restrict__ out) {
    float best = 3.4028235e38f;
    for (int i = threadIdx.x; i < n; i += blockDim.x)
        best = fminf(best, partials[i]);
#pragma unroll
    for (int off = 16; off; off >>= 1)
        best = fminf(best, __shfl_xor_sync(0xffffffffu, best, off));

    __shared__ float wmin[32];
    if ((threadIdx.x & 31) == 0) wmin[threadIdx.x >> 5] = best;
    __syncthreads();
    if (threadIdx.x == 0) {
        float r = wmin[0];
        int nw = (int)(blockDim.x / 32);
        for (int i = 1; i < nw; i++) r = fminf(r, wmin[i]);
        out[0] = sqrtf(fmaxf(r, 0.0f));
    }
}

extern "C" void kernel_launch(void* const* d_in, const int* in_sizes, int n_in,
                              void* d_out, int out_size) {
    const float* v1 = (const float*)d_in[0];
    const float* v2 = (const float*)d_in[1];
    float* out = (float*)d_out;

    const int B = 16;
    const int N = in_sizes[0] / (B * 3);
    const int M = in_sizes[1] / (B * 3);

    dim3 grid((M + TM - 1) / TM, (N + TN - 1) / TN, B);
    int nblocks = (int)(grid.x * grid.y * grid.z);

    float* partials = nullptr;
    cudaGetSymbolAddress((void**)&partials, g_partials);

    pairmin_kernel<<<grid, THREADS>>>(v1, v2, B, N, M, partials);
    final_reduce_kernel<<<1, 1024>>>(partials, nblocks, out);
}

// round 2
// speedup vs baseline: 1.3238x; 1.3238x over previous
#include <cuda_runtime.h>
#include <math.h>

// MinDistLoss: out = min_{b,n,m} sqrt(max( xx[b,n] + yy[b,m] - 2*dot(v1[b,n],v2[b,m]), 0 ))
//
// FROZEN numeric scheme (matched reference with rel_err = 0.0 in round 1):
//   xx = (x0*x0 + x1*x1) + x2*x2         (separate mul/add)
//   dot = fma(z,z, fma(y,y, x*x))        (ascending fma chain)
//   sq = fma(-2, dot, xx+yy)
// Packed f32x2 ops round each half identically to scalar -> numerics unchanged.

#define TN 128
#define TM 128
#define THREADS 256
#define FLT_MAX_BITS 0x7f7fffffu

__device__ unsigned g_minbits;

__device__ __forceinline__ unsigned long long pack2(float lo, float hi) {
    unsigned long long r;
    asm("mov.b64 %0, {%1, %2};" : "=l"(r) : "f"(lo), "f"(hi));
    return r;
}
__device__ __forceinline__ void unpack2(unsigned long long v, float& lo, float& hi) {
    asm("mov.b64 {%0, %1}, %2;" : "=f"(lo), "=f"(hi) : "l"(v));
}
__device__ __forceinline__ unsigned long long mul2(unsigned long long a, unsigned long long b) {
    unsigned long long r;
    asm("mul.rn.f32x2 %0, %1, %2;" : "=l"(r) : "l"(a), "l"(b));
    return r;
}
__device__ __forceinline__ unsigned long long add2(unsigned long long a, unsigned long long b) {
    unsigned long long r;
    asm("add.rn.f32x2 %0, %1, %2;" : "=l"(r) : "l"(a), "l"(b));
    return r;
}
__device__ __forceinline__ unsigned long long fma2(unsigned long long a, unsigned long long b,
                                                   unsigned long long c) {
    unsigned long long r;
    asm("fma.rn.f32x2 %0, %1, %2, %3;" : "=l"(r) : "l"(a), "l"(b), "l"(c));
    return r;
}

__global__ void init_kernel() { g_minbits = FLT_MAX_BITS; }

__global__ __launch_bounds__(THREADS)
void pairmin_kernel(const float* __restrict__ v1, const float* __restrict__ v2,
                    int B, int N, int M) {
    __shared__ float sax[TN], say[TN], saz[TN], saw[TN];
    __shared__ float sbx[TM], sby[TM], sbz[TM], sbw[TM];

    const int b  = blockIdx.z;
    const int n0 = blockIdx.y * TN;
    const int m0 = blockIdx.x * TM;
    const float* p1 = v1 + (size_t)b * N * 3;
    const float* p2 = v2 + (size_t)b * M * 3;
    const int tid = threadIdx.x;

    // Stage tiles (clamped indices: duplicate pairs are harmless under min)
    for (int i = tid; i < TN; i += THREADS) {
        int n = n0 + i; if (n > N - 1) n = N - 1;
        float x0 = p1[n * 3 + 0], x1 = p1[n * 3 + 1], x2 = p1[n * 3 + 2];
        sax[i] = x0; say[i] = x1; saz[i] = x2;
        saw[i] = __fadd_rn(__fadd_rn(__fmul_rn(x0, x0), __fmul_rn(x1, x1)),
                           __fmul_rn(x2, x2));
    }
    for (int i = tid; i < TM; i += THREADS) {
        int m = m0 + i; if (m > M - 1) m = M - 1;
        float y0 = p2[m * 3 + 0], y1 = p2[m * 3 + 1], y2 = p2[m * 3 + 2];
        sbx[i] = y0; sby[i] = y1; sbz[i] = y2;
        sbw[i] = __fadd_rn(__fadd_rn(__fmul_rn(y0, y0), __fmul_rn(y1, y1)),
                           __fmul_rn(y2, y2));
    }
    __syncthreads();

    const int tx = tid & 15;   // m group: 8 consecutive m (4 f32x2 pairs)
    const int ty = tid >> 4;   // n group: 8 consecutive n

    // a-side scalars (8 n rows)
    float ax[8], ay[8], az[8], aw[8];
#pragma unroll
    for (int i = 0; i < 8; i++) {
        int n = ty * 8 + i;
        ax[i] = sax[n]; ay[i] = say[n]; az[i] = saz[n]; aw[i] = saw[n];
    }
    // b-side packed pairs (8 m cols = 4 pairs), aligned float2 reads
    unsigned long long bx2[4], by2[4], bz2[4], bw2[4];
#pragma unroll
    for (int jp = 0; jp < 4; jp++) {
        int p = tx * 4 + jp;
        float2 fx = reinterpret_cast<const float2*>(sbx)[p];
        float2 fy = reinterpret_cast<const float2*>(sby)[p];
        float2 fz = reinterpret_cast<const float2*>(sbz)[p];
        float2 fw = reinterpret_cast<const float2*>(sbw)[p];
        bx2[jp] = pack2(fx.x, fx.y);
        by2[jp] = pack2(fy.x, fy.y);
        bz2[jp] = pack2(fz.x, fz.y);
        bw2[jp] = pack2(fw.x, fw.y);
    }

    const unsigned long long NEG2 = 0xC0000000C0000000ULL;  // {-2.0f, -2.0f}
    float best = 3.4028235e38f;

#pragma unroll
    for (int i = 0; i < 8; i++) {
        unsigned long long axx = pack2(ax[i], ax[i]);
        unsigned long long ayy = pack2(ay[i], ay[i]);
        unsigned long long azz = pack2(az[i], az[i]);
        unsigned long long aww = pack2(aw[i], aw[i]);
#pragma unroll
        for (int jp = 0; jp < 4; jp++) {
            unsigned long long d = mul2(axx, bx2[jp]);
            d = fma2(ayy, by2[jp], d);
            d = fma2(azz, bz2[jp], d);
            unsigned long long t = add2(aww, bw2[jp]);
            unsigned long long sq = fma2(NEG2, d, t);
            float lo, hi;
            unpack2(sq, lo, hi);
            best = fminf(best, fminf(lo, hi));
        }
    }

    // Block reduce
#pragma unroll
    for (int off = 16; off; off >>= 1)
        best = fminf(best, __shfl_xor_sync(0xffffffffu, best, off));

    __shared__ float wmin[THREADS / 32];
    if ((tid & 31) == 0) wmin[tid >> 5] = best;
    __syncthreads();
    if (tid == 0) {
        float r = wmin[0];
#pragma unroll
        for (int w = 1; w < THREADS / 32; w++) r = fminf(r, wmin[w]);
        // nonneg float bits order as uint
        atomicMin(&g_minbits, __float_as_uint(fmaxf(r, 0.0f)));
    }
}

__global__ void finalize_kernel(float* __restrict__ out) {
    out[0] = sqrtf(__uint_as_float(g_minbits));
}

extern "C" void kernel_launch(void* const* d_in, const int* in_sizes, int n_in,
                              void* d_out, int out_size) {
    const float* v1 = (const float*)d_in[0];
    const float* v2 = (const float*)d_in[1];
    float* out = (float*)d_out;

    const int B = 16;
    const int N = in_sizes[0] / (B * 3);
    const int M = in_sizes[1] / (B * 3);

    dim3 grid((M + TM - 1) / TM, (N + TN - 1) / TN, B);

    init_kernel<<<1, 1>>>();
    pairmin_kernel<<<grid, THREADS>>>(v1, v2, B, N, M);
    finalize_kernel<<<1, 1>>>(out);
}